// round 13
// baseline (speedup 1.0000x reference)
#include <cuda_runtime.h>

// GATLayer: B=8, N=1024, INP=7, D=32, H=4
// Identity 1: softmax_j(s_i + s_j + ba) == softmax_j(s_j) => att independent
//   of i => output row constant per batch.
// Identity 2: |s_j| small => no max subtraction needed in fp32 softmax:
//   m[b,h,:] = sum_j e^{s_j[h]} fx[j,:] / sum_j e^{s_j[h]}
//   => aggregation = per-block partials computed inside the MLP kernel.

#define BB 8
#define NN 1024
#define DD 32
#define HH 4

// per-block partials: [128 blocks][132] = 128 (e*fx, [h][d]) + 4 (e sums)
__device__ float g_part[128 * 132];
__device__ __align__(16) float g_o[BB * DD]; // per-batch output row [8][32]

static __device__ __forceinline__ float lrelu(float t) {
    return fmaxf(t, 0.2f * t);
}

// ---------------------------------------------------------------------------
// Kernel 1: message MLP + s_j + per-block softmax-numerator partials.
// 128 blocks x 512 threads; 64 nodes/block, 16 threads per NODE PAIR
// (s = t&15, pair g = t>>4 owns nodes g and g+32):
//  Stage A (L1): lane s computes h1 units [4s,4s+4) for both nodes -> sh1
//  Stage B (L2): lane s computes h2 units [4s,4s+4) for both nodes -> sh2
//  Stage C (L3): lane s computes fx dims  [2s,2s+2) for both nodes
// Every weight LDS feeds 2 nodes; 16-lane geometry is naturally conflict-free
// (16 x float4 = 2 phases covering all banks; the warp's two pairs read
// identical weight addresses -> broadcast merge). 4 warps/SMSP for latency
// hiding. sh1/sh2 alias the epilogue transpose via a union (barrier-guarded).
// ---------------------------------------------------------------------------
#define HSTR 68
#define TSTR 65

__global__ __launch_bounds__(512) void k_mlp(
    const float* __restrict__ x,
    const float* __restrict__ W1, const float* __restrict__ b1,
    const float* __restrict__ W2, const float* __restrict__ b2,
    const float* __restrict__ W3, const float* __restrict__ b3,
    const float* __restrict__ Wa)
{
    __shared__ float sW1[7 * 64];
    __shared__ float sW2[64 * 64];
    __shared__ float sW3[64 * 32];
    __shared__ float sWaj[32 * 4];       // Wa rows 32..63, [d][h]
    __shared__ float sb1[64], sb2[64], sb3[32];
    __shared__ float sx[448];            // x for this block's 64 nodes
    __shared__ union UU {
        struct { float sh1[64 * HSTR]; float sh2[64 * HSTR]; } a;  // 8704 f
        struct { float stmp[128 * TSTR + TSTR]; float stz[5 * TSTR]; } r;
    } u;

    const int t = threadIdx.x;

    // ---- stage weights + x ----
    {
        float4* d2 = (float4*)sW2; const float4* s2 = (const float4*)W2;
        d2[t] = s2[t]; d2[t + 512] = s2[t + 512];
        ((float4*)sW3)[t] = ((const float4*)W3)[t];
        if (t < 112) ((float4*)sW1)[t] = ((const float4*)W1)[t];
        else if (t < 144) ((float4*)sWaj)[t - 112] = ((const float4*)(Wa + 128))[t - 112];
        else if (t < 160) ((float4*)sb1)[t - 144] = ((const float4*)b1)[t - 144];
        else if (t < 176) ((float4*)sb2)[t - 160] = ((const float4*)b2)[t - 160];
        else if (t < 184) ((float4*)sb3)[t - 176] = ((const float4*)b3)[t - 176];
        else if (t >= 400) ((float4*)sx)[t - 400] = ((const float4*)(x + blockIdx.x * 448))[t - 400];
    }
    __syncthreads();

    const int g = t >> 4;                // pair 0..31 (nodes g, g+32)
    const int s = t & 15;

    // ---- Stage A: layer 1, units [4s,4s+4) for both nodes ----
    {
        float xv0[7], xv1[7];
#pragma unroll
        for (int k = 0; k < 7; k++) { xv0[k] = sx[g * 7 + k]; xv1[k] = sx[(g + 32) * 7 + k]; }

        const float4 b = ((const float4*)sb1)[s];
        float n0 = b.x, n1 = b.y, n2 = b.z, n3 = b.w;
        float m0 = b.x, m1 = b.y, m2 = b.z, m3 = b.w;
#pragma unroll
        for (int k = 0; k < 7; k++) {
            const float xk0 = xv0[k], xk1 = xv1[k];
            const float4 w = ((const float4*)(sW1 + k * 64))[s];
            n0 += xk0 * w.x; n1 += xk0 * w.y; n2 += xk0 * w.z; n3 += xk0 * w.w;
            m0 += xk1 * w.x; m1 += xk1 * w.y; m2 += xk1 * w.z; m3 += xk1 * w.w;
        }
        *(float4*)(u.a.sh1 + g * HSTR + 4 * s) =
            make_float4(lrelu(n0), lrelu(n1), lrelu(n2), lrelu(n3));
        *(float4*)(u.a.sh1 + (g + 32) * HSTR + 4 * s) =
            make_float4(lrelu(m0), lrelu(m1), lrelu(m2), lrelu(m3));
    }
    __syncthreads();

    // ---- Stage B: layer 2, units [4s,4s+4) for both nodes ----
    {
        const float4 b = ((const float4*)sb2)[s];
        float n0 = b.x, n1 = b.y, n2 = b.z, n3 = b.w;
        float m0 = b.x, m1 = b.y, m2 = b.z, m3 = b.w;
        const float* h0 = u.a.sh1 + g * HSTR;
        const float* h1 = u.a.sh1 + (g + 32) * HSTR;
#pragma unroll
        for (int k = 0; k < 64; k += 2) {
            const float2 a0 = *(const float2*)(h0 + k);
            const float2 a1 = *(const float2*)(h1 + k);
            const float4 w0 = ((const float4*)(sW2 + k * 64))[s];
            const float4 w1 = ((const float4*)(sW2 + (k + 1) * 64))[s];
            n0 += a0.x * w0.x; n1 += a0.x * w0.y; n2 += a0.x * w0.z; n3 += a0.x * w0.w;
            m0 += a1.x * w0.x; m1 += a1.x * w0.y; m2 += a1.x * w0.z; m3 += a1.x * w0.w;
            n0 += a0.y * w1.x; n1 += a0.y * w1.y; n2 += a0.y * w1.z; n3 += a0.y * w1.w;
            m0 += a1.y * w1.x; m1 += a1.y * w1.y; m2 += a1.y * w1.z; m3 += a1.y * w1.w;
        }
        *(float4*)(u.a.sh2 + g * HSTR + 4 * s) =
            make_float4(lrelu(n0), lrelu(n1), lrelu(n2), lrelu(n3));
        *(float4*)(u.a.sh2 + (g + 32) * HSTR + 4 * s) =
            make_float4(lrelu(m0), lrelu(m1), lrelu(m2), lrelu(m3));
    }
    __syncthreads();

    // ---- Stage C: layer 3, dims [2s,2s+2) for both nodes ----
    float f0, f1;               // node0 fx dims 2s, 2s+1
    float q0, q1;               // node1
    {
        const float2 b3v = *(const float2*)(sb3 + 2 * s);
        float ve0 = b3v.x, ve1 = b3v.y, vo0 = 0.f, vo1 = 0.f;
        float ue0 = b3v.x, ue1 = b3v.y, uo0 = 0.f, uo1 = 0.f;
        const float* h0 = u.a.sh2 + g * HSTR;
        const float* h1 = u.a.sh2 + (g + 32) * HSTR;
#pragma unroll
        for (int j = 0; j < 64; j += 2) {
            const float2 ha = *(const float2*)(h0 + j);
            const float2 hb = *(const float2*)(h1 + j);
            const float2 w0 = *(const float2*)(sW3 + j * 32 + 2 * s);
            const float2 w1 = *(const float2*)(sW3 + (j + 1) * 32 + 2 * s);
            ve0 += ha.x * w0.x; ve1 += ha.x * w0.y;
            vo0 += ha.y * w1.x; vo1 += ha.y * w1.y;
            ue0 += hb.x * w0.x; ue1 += hb.x * w0.y;
            uo0 += hb.y * w1.x; uo1 += hb.y * w1.y;
        }
        f0 = ve0 + vo0; f1 = ve1 + vo1;
        q0 = ue0 + uo0; q1 = ue1 + uo1;
    }

    // ---- s_j = fx @ Wa[D:]: partials over lane's 2 dims, 16-lane all-reduce
    float sj0, sj1, sj2, sj3;   // node0
    float tj0, tj1, tj2, tj3;   // node1
    {
        const float4 wa0 = ((const float4*)sWaj)[2 * s];
        const float4 wa1 = ((const float4*)sWaj)[2 * s + 1];
        sj0 = f0 * wa0.x + f1 * wa1.x;
        sj1 = f0 * wa0.y + f1 * wa1.y;
        sj2 = f0 * wa0.z + f1 * wa1.z;
        sj3 = f0 * wa0.w + f1 * wa1.w;
        tj0 = q0 * wa0.x + q1 * wa1.x;
        tj1 = q0 * wa0.y + q1 * wa1.y;
        tj2 = q0 * wa0.z + q1 * wa1.z;
        tj3 = q0 * wa0.w + q1 * wa1.w;
    }
#pragma unroll
    for (int o = 1; o < 16; o <<= 1) {
        sj0 += __shfl_xor_sync(0xffffffffu, sj0, o);
        sj1 += __shfl_xor_sync(0xffffffffu, sj1, o);
        sj2 += __shfl_xor_sync(0xffffffffu, sj2, o);
        sj3 += __shfl_xor_sync(0xffffffffu, sj3, o);
        tj0 += __shfl_xor_sync(0xffffffffu, tj0, o);
        tj1 += __shfl_xor_sync(0xffffffffu, tj1, o);
        tj2 += __shfl_xor_sync(0xffffffffu, tj2, o);
        tj3 += __shfl_xor_sync(0xffffffffu, tj3, o);
    }

    // sh1/sh2 dead; stmp aliases them — barrier before reuse
    __syncthreads();

    // ---- Epilogue: e = exp(s); transpose e*fx into stmp (stride 65:
    // bank = (2s+i + col) mod 32; within a warp the two pairs have adjacent
    // cols (g even/odd) -> parity classes cover all 32 banks; conflict-free.
    // node0 at col g, node1 at col g+33.
    {
        const float ea0 = __expf(sj0), ea1 = __expf(sj1);
        const float ea2 = __expf(sj2), ea3 = __expf(sj3);
        const float eb0 = __expf(tj0), eb1 = __expf(tj1);
        const float eb2 = __expf(tj2), eb3 = __expf(tj3);
        const int col = 2 * s;
        float* st = u.r.stmp;
#pragma unroll
        for (int h = 0; h < 4; h++) {
            const float ea = (h == 0) ? ea0 : (h == 1) ? ea1 : (h == 2) ? ea2 : ea3;
            const float eb = (h == 0) ? eb0 : (h == 1) ? eb1 : (h == 2) ? eb2 : eb3;
            st[(h * 32 + col + 0) * TSTR + g] = ea * f0;
            st[(h * 32 + col + 1) * TSTR + g] = ea * f1;
            st[(h * 32 + col + 0) * TSTR + g + 33] = eb * q0;
            st[(h * 32 + col + 1) * TSTR + g + 33] = eb * q1;
        }
        if (s == 0) {
            u.r.stz[0 * TSTR + g] = ea0; u.r.stz[0 * TSTR + g + 33] = eb0;
            u.r.stz[1 * TSTR + g] = ea1; u.r.stz[1 * TSTR + g + 33] = eb1;
            u.r.stz[2 * TSTR + g] = ea2; u.r.stz[2 * TSTR + g + 33] = eb2;
            u.r.stz[3 * TSTR + g] = ea3; u.r.stz[3 * TSTR + g + 33] = eb3;
        }
    }
    __syncthreads();

    // ---- block reduction over 64 nodes -> partial row [128 + 4] ----
    if (t < 128) {
        const float* col = u.r.stmp + t * TSTR;
        float a0 = 0.f, a1 = 0.f, a2 = 0.f, a3 = 0.f;
#pragma unroll
        for (int n = 0; n < 32; n += 4) {
            a0 += col[n + 0]; a1 += col[n + 1];
            a2 += col[n + 2]; a3 += col[n + 3];
        }
#pragma unroll
        for (int n = 33; n < 65; n += 4) {
            a0 += col[n + 0]; a1 += col[n + 1];
            a2 += col[n + 2]; a3 += col[n + 3];
        }
        g_part[blockIdx.x * 132 + t] = (a0 + a1) + (a2 + a3);
    } else if (t < 132) {
        const float* col = u.r.stz + (t - 128) * TSTR;
        float a0 = 0.f, a1 = 0.f, a2 = 0.f, a3 = 0.f;
#pragma unroll
        for (int n = 0; n < 32; n += 4) {
            a0 += col[n + 0]; a1 += col[n + 1];
            a2 += col[n + 2]; a3 += col[n + 3];
        }
#pragma unroll
        for (int n = 33; n < 65; n += 4) {
            a0 += col[n + 0]; a1 += col[n + 1];
            a2 += col[n + 2]; a3 += col[n + 3];
        }
        g_part[blockIdx.x * 132 + t] = (a0 + a1) + (a2 + a3);
    }
}

// ---------------------------------------------------------------------------
// Kernel 2: per-batch combine of the 16 partial rows, normalize, projection.
// 8 blocks x 128 threads.
// ---------------------------------------------------------------------------
__global__ __launch_bounds__(128) void k_final(
    const float* __restrict__ Ws, const float* __restrict__ bs)
{
    const int b = blockIdx.x;
    const int t = threadIdx.x;

    __shared__ float sm[128];
    __shared__ float zz[4];
    __shared__ float pr2[128];

    // sum this batch's 16 block-partials for component t
    const float* p = g_part + (b * 16) * 132 + t;
    float a0 = 0.f, a1 = 0.f, a2 = 0.f, a3 = 0.f;
#pragma unroll
    for (int q = 0; q < 16; q += 4) {
        a0 += p[(q + 0) * 132];
        a1 += p[(q + 1) * 132];
        a2 += p[(q + 2) * 132];
        a3 += p[(q + 3) * 132];
    }
    const float msum = (a0 + a1) + (a2 + a3);

    if (t < 4) {
        const float* pz = g_part + (b * 16) * 132 + 128 + t;
        float z0 = 0.f, z1 = 0.f, z2 = 0.f, z3 = 0.f;
#pragma unroll
        for (int q = 0; q < 16; q += 4) {
            z0 += pz[(q + 0) * 132];
            z1 += pz[(q + 1) * 132];
            z2 += pz[(q + 2) * 132];
            z3 += pz[(q + 3) * 132];
        }
        zz[t] = (z0 + z1) + (z2 + z3);
    }
    __syncthreads();

    sm[t] = msum / zz[t >> 5];
    __syncthreads();

    // projection: o[d] = bs[d] + sum_k sm[k] * Ws[k][d], 4-way k split
    const int kg = t >> 5, dd = t & 31;
    float a = 0.f;
#pragma unroll
    for (int kk = 0; kk < 32; kk++) {
        const int k = kg * 32 + kk;
        a += sm[k] * __ldg(Ws + k * 32 + dd);
    }
    pr2[t] = a;
    __syncthreads();
    if (t < 32)
        g_o[b * 32 + t] = __ldg(bs + t) + ((pr2[t] + pr2[t + 32]) + (pr2[t + 64] + pr2[t + 96]));
}

// ---------------------------------------------------------------------------
// Kernel 3: broadcast per-batch rows to the full [B,N,D] output.
// ---------------------------------------------------------------------------
__global__ __launch_bounds__(256) void k_bcast(float4* __restrict__ out)
{
    const int g = blockIdx.x * 256 + threadIdx.x; // float4 index
    const int b = g >> 13;                        // 8192 float4 per batch
    const int d4 = g & 7;
    out[g] = *(const float4*)(g_o + b * 32 + d4 * 4);
}

extern "C" void kernel_launch(void* const* d_in, const int* in_sizes, int n_in,
                              void* d_out, int out_size)
{
    const float* x  = (const float*)d_in[0];
    const float* W1 = (const float*)d_in[1];
    const float* b1 = (const float*)d_in[2];
    const float* W2 = (const float*)d_in[3];
    const float* b2 = (const float*)d_in[4];
    const float* W3 = (const float*)d_in[5];
    const float* b3 = (const float*)d_in[6];
    const float* Wa = (const float*)d_in[7];
    // d_in[8] = ba: cancels in the softmax
    const float* Ws = (const float*)d_in[9];
    const float* bs = (const float*)d_in[10];

    k_mlp<<<128, 512>>>(x, W1, b1, W2, b2, W3, b3, Wa);
    k_final<<<8, 128>>>(Ws, bs);
    k_bcast<<<256, 256>>>((float4*)d_out);
}

// round 14
// speedup vs baseline: 1.0042x; 1.0042x over previous
#include <cuda_runtime.h>

// GATLayer: B=8, N=1024, INP=7, D=32, H=4
// Identity 1: softmax_j(s_i + s_j + ba) == softmax_j(s_j) => att independent
//   of i => output row constant per batch.
// Identity 2: |s_j| small => no max subtraction needed in fp32 softmax:
//   m[b,h,:] = sum_j e^{s_j[h]} fx[j,:] / sum_j e^{s_j[h]}
//   => aggregation = per-block partials computed inside the MLP kernel.

#define BB 8
#define NN 1024
#define DD 32
#define HH 4

// per-block partials: [128 blocks][132] = 128 (e*fx, [h][d]) + 4 (e sums)
__device__ float g_part[128 * 132];
__device__ __align__(16) float g_o[BB * DD]; // per-batch output row [8][32]

static __device__ __forceinline__ float lrelu(float t) {
    return fmaxf(t, 0.2f * t);
}

// ---------------------------------------------------------------------------
// Kernel 1: message MLP + s_j + per-block softmax-numerator partials.
// 128 blocks x 256 threads; 64 nodes/block, 8 threads per NODE PAIR
// (s = t&7, group g = t>>3 owns nodes g and g+32); weight LDS.128 feeds
// 16 FFMA (2 nodes x 8). Stages B/C process TWO INDEPENDENT k-half chains
// (k and k+32) with separate accumulator sets merged at the end — 2+ loads
// in flight per warp, hiding the 29-cyc LDS latency (more warps alone did
// not help: R13 showed issue% flat at 4 warps/SMSP).
// Accumulators are scalars bound to fixed column groups (A<->2s+rot,
// B<->2s+1-rot, rot=s>>2) so nothing spills; rotation lives only in addresses.
// sh1/sh2 alias the epilogue transpose via a union (barrier separates uses).
// ---------------------------------------------------------------------------
#define HSTR 68
#define TSTR 65

__global__ __launch_bounds__(256) void k_mlp(
    const float* __restrict__ x,
    const float* __restrict__ W1, const float* __restrict__ b1,
    const float* __restrict__ W2, const float* __restrict__ b2,
    const float* __restrict__ W3, const float* __restrict__ b3,
    const float* __restrict__ Wa)
{
    __shared__ float sW1[7 * 64];
    __shared__ float sW2[64 * 64];
    __shared__ float sW3[64 * 32];
    __shared__ float sWaj[32 * 4];       // Wa rows 32..63, [d][h]
    __shared__ float sb1[64], sb2[64], sb3[32];
    __shared__ float sx[448];            // x for this block's 64 nodes
    __shared__ union UU {
        struct { float sh1[64 * HSTR]; float sh2[64 * HSTR]; } a;  // 8704 f
        struct { float stmp[128 * TSTR + TSTR]; float stz[5 * TSTR]; } r;
    } u;

    const int t = threadIdx.x;

    // ---- stage weights + x ----
    {
        float4* d2 = (float4*)sW2; const float4* s2 = (const float4*)W2;
#pragma unroll
        for (int i = 0; i < 4; i++) d2[t + i * 256] = s2[t + i * 256];
        float4* d3 = (float4*)sW3; const float4* s3 = (const float4*)W3;
#pragma unroll
        for (int i = 0; i < 2; i++) d3[t + i * 256] = s3[t + i * 256];
        if (t < 112) {
            ((float4*)sW1)[t] = ((const float4*)W1)[t];
            ((float4*)sx)[t] = ((const float4*)(x + blockIdx.x * 448))[t];
        }
        else if (t < 144) ((float4*)sWaj)[t - 112] = ((const float4*)(Wa + 128))[t - 112];
        else if (t < 160) ((float4*)sb1)[t - 144] = ((const float4*)b1)[t - 144];
        else if (t < 176) ((float4*)sb2)[t - 160] = ((const float4*)b2)[t - 160];
        else if (t < 184) ((float4*)sb3)[t - 176] = ((const float4*)b3)[t - 176];
    }
    __syncthreads();

    const int g = t >> 3;                // node group 0..31 (nodes g, g+32)
    const int s = t & 7;
    const int rot = s >> 2;              // 0/1
    const int cgA = 2 * s + rot;         // accumulator A's column group
    const int cgB = 2 * s + 1 - rot;     // accumulator B's column group

    // ---- Stage A: layer 1 for both nodes ----
    {
        float xv0[7], xv1[7];
#pragma unroll
        for (int k = 0; k < 7; k++) { xv0[k] = sx[g * 7 + k]; xv1[k] = sx[(g + 32) * 7 + k]; }

        const float4 bA = ((const float4*)sb1)[cgA];
        const float4 bB = ((const float4*)sb1)[cgB];
        float nA0 = bA.x, nA1 = bA.y, nA2 = bA.z, nA3 = bA.w;
        float nB0 = bB.x, nB1 = bB.y, nB2 = bB.z, nB3 = bB.w;
        float mA0 = bA.x, mA1 = bA.y, mA2 = bA.z, mA3 = bA.w;
        float mB0 = bB.x, mB1 = bB.y, mB2 = bB.z, mB3 = bB.w;
#pragma unroll
        for (int k = 0; k < 7; k++) {
            const float xk0 = xv0[k], xk1 = xv1[k];
            const float4* row = (const float4*)(sW1 + k * 64);
            const float4 wA = row[cgA];
            const float4 wB = row[cgB];
            nA0 += xk0 * wA.x; nA1 += xk0 * wA.y; nA2 += xk0 * wA.z; nA3 += xk0 * wA.w;
            nB0 += xk0 * wB.x; nB1 += xk0 * wB.y; nB2 += xk0 * wB.z; nB3 += xk0 * wB.w;
            mA0 += xk1 * wA.x; mA1 += xk1 * wA.y; mA2 += xk1 * wA.z; mA3 += xk1 * wA.w;
            mB0 += xk1 * wB.x; mB1 += xk1 * wB.y; mB2 += xk1 * wB.z; mB3 += xk1 * wB.w;
        }
        float4* o0 = (float4*)(u.a.sh1 + g * HSTR + 8 * s);
        float4* o1 = (float4*)(u.a.sh1 + (g + 32) * HSTR + 8 * s);
        o0[rot]     = make_float4(lrelu(nA0), lrelu(nA1), lrelu(nA2), lrelu(nA3));
        o0[1 - rot] = make_float4(lrelu(nB0), lrelu(nB1), lrelu(nB2), lrelu(nB3));
        o1[rot]     = make_float4(lrelu(mA0), lrelu(mA1), lrelu(mA2), lrelu(mA3));
        o1[1 - rot] = make_float4(lrelu(mB0), lrelu(mB1), lrelu(mB2), lrelu(mB3));
    }
    __syncthreads();

    // ---- Stage B: layer 2 for both nodes, 2 independent k-half chains ----
    {
        const float4 bA = ((const float4*)sb2)[cgA];
        const float4 bB = ((const float4*)sb2)[cgB];
        // chain 1 (k in [0,32)) carries the bias
        float nA0 = bA.x, nA1 = bA.y, nA2 = bA.z, nA3 = bA.w;
        float nB0 = bB.x, nB1 = bB.y, nB2 = bB.z, nB3 = bB.w;
        float mA0 = bA.x, mA1 = bA.y, mA2 = bA.z, mA3 = bA.w;
        float mB0 = bB.x, mB1 = bB.y, mB2 = bB.z, mB3 = bB.w;
        // chain 2 (k in [32,64)) zero-initialized
        float pA0 = 0.f, pA1 = 0.f, pA2 = 0.f, pA3 = 0.f;
        float pB0 = 0.f, pB1 = 0.f, pB2 = 0.f, pB3 = 0.f;
        float qA0 = 0.f, qA1 = 0.f, qA2 = 0.f, qA3 = 0.f;
        float qB0 = 0.f, qB1 = 0.f, qB2 = 0.f, qB3 = 0.f;
        const float* h1r0 = u.a.sh1 + g * HSTR;
        const float* h1r1 = u.a.sh1 + (g + 32) * HSTR;
#pragma unroll
        for (int k = 0; k < 32; k += 2) {
            // independent loads for both chains up front
            const float2 ha0 = *(const float2*)(h1r0 + k);
            const float2 ha1 = *(const float2*)(h1r1 + k);
            const float2 hb0 = *(const float2*)(h1r0 + k + 32);
            const float2 hb1 = *(const float2*)(h1r1 + k + 32);
            const float4* r0 = (const float4*)(sW2 + k * 64);
            const float4* r1 = (const float4*)(sW2 + (k + 1) * 64);
            const float4* r2 = (const float4*)(sW2 + (k + 32) * 64);
            const float4* r3 = (const float4*)(sW2 + (k + 33) * 64);
            const float4 wA0 = r0[cgA], wB0 = r0[cgB];
            const float4 wA2 = r2[cgA], wB2 = r2[cgB];
            const float4 wA1 = r1[cgA], wB1 = r1[cgB];
            const float4 wA3 = r3[cgA], wB3 = r3[cgB];
            // chain 1, k
            nA0 += ha0.x * wA0.x; nA1 += ha0.x * wA0.y; nA2 += ha0.x * wA0.z; nA3 += ha0.x * wA0.w;
            nB0 += ha0.x * wB0.x; nB1 += ha0.x * wB0.y; nB2 += ha0.x * wB0.z; nB3 += ha0.x * wB0.w;
            mA0 += ha1.x * wA0.x; mA1 += ha1.x * wA0.y; mA2 += ha1.x * wA0.z; mA3 += ha1.x * wA0.w;
            mB0 += ha1.x * wB0.x; mB1 += ha1.x * wB0.y; mB2 += ha1.x * wB0.z; mB3 += ha1.x * wB0.w;
            // chain 2, k+32
            pA0 += hb0.x * wA2.x; pA1 += hb0.x * wA2.y; pA2 += hb0.x * wA2.z; pA3 += hb0.x * wA2.w;
            pB0 += hb0.x * wB2.x; pB1 += hb0.x * wB2.y; pB2 += hb0.x * wB2.z; pB3 += hb0.x * wB2.w;
            qA0 += hb1.x * wA2.x; qA1 += hb1.x * wA2.y; qA2 += hb1.x * wA2.z; qA3 += hb1.x * wA2.w;
            qB0 += hb1.x * wB2.x; qB1 += hb1.x * wB2.y; qB2 += hb1.x * wB2.z; qB3 += hb1.x * wB2.w;
            // chain 1, k+1
            nA0 += ha0.y * wA1.x; nA1 += ha0.y * wA1.y; nA2 += ha0.y * wA1.z; nA3 += ha0.y * wA1.w;
            nB0 += ha0.y * wB1.x; nB1 += ha0.y * wB1.y; nB2 += ha0.y * wB1.z; nB3 += ha0.y * wB1.w;
            mA0 += ha1.y * wA1.x; mA1 += ha1.y * wA1.y; mA2 += ha1.y * wA1.z; mA3 += ha1.y * wA1.w;
            mB0 += ha1.y * wB1.x; mB1 += ha1.y * wB1.y; mB2 += ha1.y * wB1.z; mB3 += ha1.y * wB1.w;
            // chain 2, k+33
            pA0 += hb0.y * wA3.x; pA1 += hb0.y * wA3.y; pA2 += hb0.y * wA3.z; pA3 += hb0.y * wA3.w;
            pB0 += hb0.y * wB3.x; pB1 += hb0.y * wB3.y; pB2 += hb0.y * wB3.z; pB3 += hb0.y * wB3.w;
            qA0 += hb1.y * wA3.x; qA1 += hb1.y * wA3.y; qA2 += hb1.y * wA3.z; qA3 += hb1.y * wA3.w;
            qB0 += hb1.y * wB3.x; qB1 += hb1.y * wB3.y; qB2 += hb1.y * wB3.z; qB3 += hb1.y * wB3.w;
        }
        float4* o0 = (float4*)(u.a.sh2 + g * HSTR + 8 * s);
        float4* o1 = (float4*)(u.a.sh2 + (g + 32) * HSTR + 8 * s);
        o0[rot]     = make_float4(lrelu(nA0 + pA0), lrelu(nA1 + pA1), lrelu(nA2 + pA2), lrelu(nA3 + pA3));
        o0[1 - rot] = make_float4(lrelu(nB0 + pB0), lrelu(nB1 + pB1), lrelu(nB2 + pB2), lrelu(nB3 + pB3));
        o1[rot]     = make_float4(lrelu(mA0 + qA0), lrelu(mA1 + qA1), lrelu(mA2 + qA2), lrelu(mA3 + qA3));
        o1[1 - rot] = make_float4(lrelu(mB0 + qB0), lrelu(mB1 + qB1), lrelu(mB2 + qB2), lrelu(mB3 + qB3));
    }
    __syncthreads();

    // ---- Stage C: layer 3, dims [4s,4s+4), 2 nodes x 2 j-half chains ----
    float f0, f1, f2, f3;       // node0 fx
    float q0, q1, q2, q3;       // node1 fx
    {
        const float4 b3v = ((const float4*)sb3)[s];
        // chain 1: j in [0,32)
        float e0 = b3v.x, e1 = b3v.y, e2 = b3v.z, e3 = b3v.w;
        float u0 = b3v.x, u1 = b3v.y, u2 = b3v.z, u3 = b3v.w;
        // chain 2: j in [32,64)
        float c0 = 0.f, c1 = 0.f, c2 = 0.f, c3 = 0.f;
        float d0 = 0.f, d1 = 0.f, d2 = 0.f, d3 = 0.f;
        const float* h2r0 = u.a.sh2 + g * HSTR;
        const float* h2r1 = u.a.sh2 + (g + 32) * HSTR;
#pragma unroll
        for (int j = 0; j < 32; j += 2) {
            const float2 ha = *(const float2*)(h2r0 + j);
            const float2 hb = *(const float2*)(h2r1 + j);
            const float2 hc = *(const float2*)(h2r0 + j + 32);
            const float2 hd = *(const float2*)(h2r1 + j + 32);
            const float4 w0 = ((const float4*)sW3)[j * 8 + s];
            const float4 w1 = ((const float4*)sW3)[(j + 1) * 8 + s];
            const float4 w2 = ((const float4*)sW3)[(j + 32) * 8 + s];
            const float4 w3 = ((const float4*)sW3)[(j + 33) * 8 + s];
            e0 += ha.x * w0.x; e1 += ha.x * w0.y; e2 += ha.x * w0.z; e3 += ha.x * w0.w;
            u0 += hb.x * w0.x; u1 += hb.x * w0.y; u2 += hb.x * w0.z; u3 += hb.x * w0.w;
            c0 += hc.x * w2.x; c1 += hc.x * w2.y; c2 += hc.x * w2.z; c3 += hc.x * w2.w;
            d0 += hd.x * w2.x; d1 += hd.x * w2.y; d2 += hd.x * w2.z; d3 += hd.x * w2.w;
            e0 += ha.y * w1.x; e1 += ha.y * w1.y; e2 += ha.y * w1.z; e3 += ha.y * w1.w;
            u0 += hb.y * w1.x; u1 += hb.y * w1.y; u2 += hb.y * w1.z; u3 += hb.y * w1.w;
            c0 += hc.y * w3.x; c1 += hc.y * w3.y; c2 += hc.y * w3.z; c3 += hc.y * w3.w;
            d0 += hd.y * w3.x; d1 += hd.y * w3.y; d2 += hd.y * w3.z; d3 += hd.y * w3.w;
        }
        f0 = e0 + c0; f1 = e1 + c1; f2 = e2 + c2; f3 = e3 + c3;
        q0 = u0 + d0; q1 = u1 + d1; q2 = u2 + d2; q3 = u3 + d3;
    }

    // ---- s_j = fx @ Wa[D:]: partials over lane's 4 dims, 8-lane all-reduce
    float sj0, sj1, sj2, sj3;   // node0
    float tj0, tj1, tj2, tj3;   // node1
    {
        const float4 w0 = ((const float4*)sWaj)[4 * s + 0];
        const float4 w1 = ((const float4*)sWaj)[4 * s + 1];
        const float4 w2 = ((const float4*)sWaj)[4 * s + 2];
        const float4 w3 = ((const float4*)sWaj)[4 * s + 3];
        sj0 = f0 * w0.x + f1 * w1.x + f2 * w2.x + f3 * w3.x;
        sj1 = f0 * w0.y + f1 * w1.y + f2 * w2.y + f3 * w3.y;
        sj2 = f0 * w0.z + f1 * w1.z + f2 * w2.z + f3 * w3.z;
        sj3 = f0 * w0.w + f1 * w1.w + f2 * w2.w + f3 * w3.w;
        tj0 = q0 * w0.x + q1 * w1.x + q2 * w2.x + q3 * w3.x;
        tj1 = q0 * w0.y + q1 * w1.y + q2 * w2.y + q3 * w3.y;
        tj2 = q0 * w0.z + q1 * w1.z + q2 * w2.z + q3 * w3.z;
        tj3 = q0 * w0.w + q1 * w1.w + q2 * w2.w + q3 * w3.w;
    }
#pragma unroll
    for (int o = 1; o < 8; o <<= 1) {
        sj0 += __shfl_xor_sync(0xffffffffu, sj0, o);
        sj1 += __shfl_xor_sync(0xffffffffu, sj1, o);
        sj2 += __shfl_xor_sync(0xffffffffu, sj2, o);
        sj3 += __shfl_xor_sync(0xffffffffu, sj3, o);
        tj0 += __shfl_xor_sync(0xffffffffu, tj0, o);
        tj1 += __shfl_xor_sync(0xffffffffu, tj1, o);
        tj2 += __shfl_xor_sync(0xffffffffu, tj2, o);
        tj3 += __shfl_xor_sync(0xffffffffu, tj3, o);
    }

    // sh1/sh2 are dead, stmp aliases them: barrier before reuse
    __syncthreads();

    // ---- Epilogue: e = exp(s); transpose e*fx into stmp (stride 65:
    // bank = (4s + i + col) % 32, conflict-free; node0 col g, node1 col g+33)
    {
        const float ea0 = __expf(sj0), ea1 = __expf(sj1);
        const float ea2 = __expf(sj2), ea3 = __expf(sj3);
        const float eb0 = __expf(tj0), eb1 = __expf(tj1);
        const float eb2 = __expf(tj2), eb3 = __expf(tj3);
        const int col = 4 * s;
        float* st = u.r.stmp;
#pragma unroll
        for (int h = 0; h < 4; h++) {
            const float eh = (h == 0) ? ea0 : (h == 1) ? ea1 : (h == 2) ? ea2 : ea3;
            st[(h * 32 + col + 0) * TSTR + g] = eh * f0;
            st[(h * 32 + col + 1) * TSTR + g] = eh * f1;
            st[(h * 32 + col + 2) * TSTR + g] = eh * f2;
            st[(h * 32 + col + 3) * TSTR + g] = eh * f3;
        }
#pragma unroll
        for (int h = 0; h < 4; h++) {
            const float eh = (h == 0) ? eb0 : (h == 1) ? eb1 : (h == 2) ? eb2 : eb3;
            st[(h * 32 + col + 0) * TSTR + g + 33] = eh * q0;
            st[(h * 32 + col + 1) * TSTR + g + 33] = eh * q1;
            st[(h * 32 + col + 2) * TSTR + g + 33] = eh * q2;
            st[(h * 32 + col + 3) * TSTR + g + 33] = eh * q3;
        }
        if (s == 0) {
            u.r.stz[0 * TSTR + g] = ea0; u.r.stz[0 * TSTR + g + 33] = eb0;
            u.r.stz[1 * TSTR + g] = ea1; u.r.stz[1 * TSTR + g + 33] = eb1;
            u.r.stz[2 * TSTR + g] = ea2; u.r.stz[2 * TSTR + g + 33] = eb2;
            u.r.stz[3 * TSTR + g] = ea3; u.r.stz[3 * TSTR + g + 33] = eb3;
        }
    }
    __syncthreads();

    // ---- block reduction over 64 nodes -> partial row [128 + 4] ----
    if (t < 128) {
        const float* col = u.r.stmp + t * TSTR;
        float a0 = 0.f, a1 = 0.f, a2 = 0.f, a3 = 0.f;
#pragma unroll
        for (int n = 0; n < 32; n += 4) {
            a0 += col[n + 0]; a1 += col[n + 1];
            a2 += col[n + 2]; a3 += col[n + 3];
        }
#pragma unroll
        for (int n = 33; n < 65; n += 4) {
            a0 += col[n + 0]; a1 += col[n + 1];
            a2 += col[n + 2]; a3 += col[n + 3];
        }
        g_part[blockIdx.x * 132 + t] = (a0 + a1) + (a2 + a3);
    } else if (t < 132) {
        const float* col = u.r.stz + (t - 128) * TSTR;
        float a0 = 0.f, a1 = 0.f, a2 = 0.f, a3 = 0.f;
#pragma unroll
        for (int n = 0; n < 32; n += 4) {
            a0 += col[n + 0]; a1 += col[n + 1];
            a2 += col[n + 2]; a3 += col[n + 3];
        }
#pragma unroll
        for (int n = 33; n < 65; n += 4) {
            a0 += col[n + 0]; a1 += col[n + 1];
            a2 += col[n + 2]; a3 += col[n + 3];
        }
        g_part[blockIdx.x * 132 + t] = (a0 + a1) + (a2 + a3);
    }
}

// ---------------------------------------------------------------------------
// Kernel 2: per-batch combine of the 16 partial rows, normalize, projection.
// 8 blocks x 128 threads.
// ---------------------------------------------------------------------------
__global__ __launch_bounds__(128) void k_final(
    const float* __restrict__ Ws, const float* __restrict__ bs)
{
    const int b = blockIdx.x;
    const int t = threadIdx.x;

    __shared__ float sm[128];
    __shared__ float zz[4];
    __shared__ float pr2[128];

    // sum this batch's 16 block-partials for component t
    const float* p = g_part + (b * 16) * 132 + t;
    float a0 = 0.f, a1 = 0.f, a2 = 0.f, a3 = 0.f;
#pragma unroll
    for (int q = 0; q < 16; q += 4) {
        a0 += p[(q + 0) * 132];
        a1 += p[(q + 1) * 132];
        a2 += p[(q + 2) * 132];
        a3 += p[(q + 3) * 132];
    }
    const float msum = (a0 + a1) + (a2 + a3);

    if (t < 4) {
        const float* pz = g_part + (b * 16) * 132 + 128 + t;
        float z0 = 0.f, z1 = 0.f, z2 = 0.f, z3 = 0.f;
#pragma unroll
        for (int q = 0; q < 16; q += 4) {
            z0 += pz[(q + 0) * 132];
            z1 += pz[(q + 1) * 132];
            z2 += pz[(q + 2) * 132];
            z3 += pz[(q + 3) * 132];
        }
        zz[t] = (z0 + z1) + (z2 + z3);
    }
    __syncthreads();

    sm[t] = msum / zz[t >> 5];
    __syncthreads();

    // projection: o[d] = bs[d] + sum_k sm[k] * Ws[k][d], 4-way k split
    const int kg = t >> 5, dd = t & 31;
    float a = 0.f;
#pragma unroll
    for (int kk = 0; kk < 32; kk++) {
        const int k = kg * 32 + kk;
        a += sm[k] * __ldg(Ws + k * 32 + dd);
    }
    pr2[t] = a;
    __syncthreads();
    if (t < 32)
        g_o[b * 32 + t] = __ldg(bs + t) + ((pr2[t] + pr2[t + 32]) + (pr2[t + 64] + pr2[t + 96]));
}

// ---------------------------------------------------------------------------
// Kernel 3: broadcast per-batch rows to the full [B,N,D] output.
// ---------------------------------------------------------------------------
__global__ __launch_bounds__(256) void k_bcast(float4* __restrict__ out)
{
    const int g = blockIdx.x * 256 + threadIdx.x; // float4 index
    const int b = g >> 13;                        // 8192 float4 per batch
    const int d4 = g & 7;
    out[g] = *(const float4*)(g_o + b * 32 + d4 * 4);
}

extern "C" void kernel_launch(void* const* d_in, const int* in_sizes, int n_in,
                              void* d_out, int out_size)
{
    const float* x  = (const float*)d_in[0];
    const float* W1 = (const float*)d_in[1];
    const float* b1 = (const float*)d_in[2];
    const float* W2 = (const float*)d_in[3];
    const float* b2 = (const float*)d_in[4];
    const float* W3 = (const float*)d_in[5];
    const float* b3 = (const float*)d_in[6];
    const float* Wa = (const float*)d_in[7];
    // d_in[8] = ba: cancels in the softmax
    const float* Ws = (const float*)d_in[9];
    const float* bs = (const float*)d_in[10];

    k_mlp<<<128, 256>>>(x, W1, b1, W2, b2, W3, b3, Wa);
    k_final<<<8, 128>>>(Ws, bs);
    k_bcast<<<256, 256>>>((float4*)d_out);
}

// round 17
// speedup vs baseline: 1.1855x; 1.1805x over previous
#include <cuda_runtime.h>

// GATLayer: B=8, N=1024, INP=7, D=32, H=4
// Identity 1: softmax_j(s_i + s_j + ba) == softmax_j(s_j) => att independent
//   of i => output row constant per batch.
// Identity 2: |s_j| small => no max subtraction needed in fp32 softmax:
//   m[b,h,:] = sum_j e^{s_j[h]} fx[j,:] / sum_j e^{s_j[h]}
// Single persistent kernel: per-block partials -> software grid barrier
// (all 128 blocks co-resident at grid 128 <= 148 SMs) -> per-block combine,
// projection (full 4096-float Ws staged in smem), output-slice write.

#define BB 8
#define NN 1024
#define DD 32
#define HH 4

// per-block partials: [128 blocks][132] = 128 (e*fx, [h][d]) + 4 (e sums)
__device__ float g_part[128 * 132];
// grid barrier: monotonic arrival counter (replay-safe; never reset)
__device__ unsigned int g_bar;

static __device__ __forceinline__ float lrelu(float t) {
    return fmaxf(t, 0.2f * t);
}

// ---------------------------------------------------------------------------
// 128 blocks x 256 threads; 64 nodes/block, 8 threads per NODE PAIR
// (s = t&7, group g = t>>3 owns nodes g and g+32); weight LDS.128 feeds
// 16 FFMA (2 nodes x 8). Accumulators are scalars bound to fixed column
// groups (A<->2s+rot, B<->2s+1-rot, rot=s>>2) so nothing spills.
// sh1/sh2 alias the epilogue transpose AND the post-barrier buffers via a
// union (barriers separate all three uses).
// ---------------------------------------------------------------------------
#define HSTR 68
#define TSTR 65

__global__ __launch_bounds__(256) void k_all(
    const float* __restrict__ x,
    const float* __restrict__ W1, const float* __restrict__ b1,
    const float* __restrict__ W2, const float* __restrict__ b2,
    const float* __restrict__ W3, const float* __restrict__ b3,
    const float* __restrict__ Wa,
    const float* __restrict__ Ws, const float* __restrict__ bs,
    float4* __restrict__ out)
{
    __shared__ float sW1[7 * 64];
    __shared__ float sW2[64 * 64];
    __shared__ float sW3[64 * 32];
    __shared__ float sWaj[32 * 4];       // Wa rows 32..63, [d][h]
    __shared__ float sb1[64], sb2[64], sb3[32];
    __shared__ float sx[448];            // x for this block's 64 nodes
    __shared__ __align__(16) union UU {
        struct { float sh1[64 * HSTR]; float sh2[64 * HSTR]; } a;           // MLP scratch (8704 f)
        struct { float stmp[128 * TSTR + TSTR]; float stz[5 * TSTR]; } r;   // transpose
        struct { float ws[4096]; float sm[128]; float zz[4];
                 float pr2[128]; float row[32]; float bsv[32]; } f;         // post-barrier (4420 f)
    } u;

    const int t = threadIdx.x;
    const int bid = blockIdx.x;

    // ---- stage weights + x ----
    {
        float4* d2 = (float4*)sW2; const float4* s2 = (const float4*)W2;
#pragma unroll
        for (int i = 0; i < 4; i++) d2[t + i * 256] = s2[t + i * 256];
        float4* d3 = (float4*)sW3; const float4* s3 = (const float4*)W3;
#pragma unroll
        for (int i = 0; i < 2; i++) d3[t + i * 256] = s3[t + i * 256];
        if (t < 112) {
            ((float4*)sW1)[t] = ((const float4*)W1)[t];
            ((float4*)sx)[t] = ((const float4*)(x + bid * 448))[t];
        }
        else if (t < 144) ((float4*)sWaj)[t - 112] = ((const float4*)(Wa + 128))[t - 112];
        else if (t < 160) ((float4*)sb1)[t - 144] = ((const float4*)b1)[t - 144];
        else if (t < 176) ((float4*)sb2)[t - 160] = ((const float4*)b2)[t - 160];
        else if (t < 184) ((float4*)sb3)[t - 176] = ((const float4*)b3)[t - 176];
    }
    __syncthreads();

    const int g = t >> 3;                // node group 0..31 (nodes g, g+32)
    const int s = t & 7;
    const int rot = s >> 2;              // 0/1
    const int cgA = 2 * s + rot;         // accumulator A's column group
    const int cgB = 2 * s + 1 - rot;     // accumulator B's column group

    // ---- Stage A: layer 1 for both nodes ----
    {
        float xv0[7], xv1[7];
#pragma unroll
        for (int k = 0; k < 7; k++) { xv0[k] = sx[g * 7 + k]; xv1[k] = sx[(g + 32) * 7 + k]; }

        const float4 bA = ((const float4*)sb1)[cgA];
        const float4 bB = ((const float4*)sb1)[cgB];
        float nA0 = bA.x, nA1 = bA.y, nA2 = bA.z, nA3 = bA.w;
        float nB0 = bB.x, nB1 = bB.y, nB2 = bB.z, nB3 = bB.w;
        float mA0 = bA.x, mA1 = bA.y, mA2 = bA.z, mA3 = bA.w;
        float mB0 = bB.x, mB1 = bB.y, mB2 = bB.z, mB3 = bB.w;
#pragma unroll
        for (int k = 0; k < 7; k++) {
            const float xk0 = xv0[k], xk1 = xv1[k];
            const float4* row = (const float4*)(sW1 + k * 64);
            const float4 wA = row[cgA];
            const float4 wB = row[cgB];
            nA0 += xk0 * wA.x; nA1 += xk0 * wA.y; nA2 += xk0 * wA.z; nA3 += xk0 * wA.w;
            nB0 += xk0 * wB.x; nB1 += xk0 * wB.y; nB2 += xk0 * wB.z; nB3 += xk0 * wB.w;
            mA0 += xk1 * wA.x; mA1 += xk1 * wA.y; mA2 += xk1 * wA.z; mA3 += xk1 * wA.w;
            mB0 += xk1 * wB.x; mB1 += xk1 * wB.y; mB2 += xk1 * wB.z; mB3 += xk1 * wB.w;
        }
        float4* o0 = (float4*)(u.a.sh1 + g * HSTR + 8 * s);
        float4* o1 = (float4*)(u.a.sh1 + (g + 32) * HSTR + 8 * s);
        o0[rot]     = make_float4(lrelu(nA0), lrelu(nA1), lrelu(nA2), lrelu(nA3));
        o0[1 - rot] = make_float4(lrelu(nB0), lrelu(nB1), lrelu(nB2), lrelu(nB3));
        o1[rot]     = make_float4(lrelu(mA0), lrelu(mA1), lrelu(mA2), lrelu(mA3));
        o1[1 - rot] = make_float4(lrelu(mB0), lrelu(mB1), lrelu(mB2), lrelu(mB3));
    }
    __syncthreads();

    // ---- Stage B: layer 2 for both nodes ----
    {
        const float4 bA = ((const float4*)sb2)[cgA];
        const float4 bB = ((const float4*)sb2)[cgB];
        float nA0 = bA.x, nA1 = bA.y, nA2 = bA.z, nA3 = bA.w;
        float nB0 = bB.x, nB1 = bB.y, nB2 = bB.z, nB3 = bB.w;
        float mA0 = bA.x, mA1 = bA.y, mA2 = bA.z, mA3 = bA.w;
        float mB0 = bB.x, mB1 = bB.y, mB2 = bB.z, mB3 = bB.w;
        const float* h1r0 = u.a.sh1 + g * HSTR;
        const float* h1r1 = u.a.sh1 + (g + 32) * HSTR;
#pragma unroll
        for (int k = 0; k < 64; k += 2) {
            const float2 hk0 = *(const float2*)(h1r0 + k);
            const float2 hk1 = *(const float2*)(h1r1 + k);
            const float4* row0 = (const float4*)(sW2 + k * 64);
            const float4* row1 = (const float4*)(sW2 + (k + 1) * 64);
            {
                const float4 wA = row0[cgA], wB = row0[cgB];
                nA0 += hk0.x * wA.x; nA1 += hk0.x * wA.y; nA2 += hk0.x * wA.z; nA3 += hk0.x * wA.w;
                nB0 += hk0.x * wB.x; nB1 += hk0.x * wB.y; nB2 += hk0.x * wB.z; nB3 += hk0.x * wB.w;
                mA0 += hk1.x * wA.x; mA1 += hk1.x * wA.y; mA2 += hk1.x * wA.z; mA3 += hk1.x * wA.w;
                mB0 += hk1.x * wB.x; mB1 += hk1.x * wB.y; mB2 += hk1.x * wB.z; mB3 += hk1.x * wB.w;
            }
            {
                const float4 wA = row1[cgA], wB = row1[cgB];
                nA0 += hk0.y * wA.x; nA1 += hk0.y * wA.y; nA2 += hk0.y * wA.z; nA3 += hk0.y * wA.w;
                nB0 += hk0.y * wB.x; nB1 += hk0.y * wB.y; nB2 += hk0.y * wB.z; nB3 += hk0.y * wB.w;
                mA0 += hk1.y * wA.x; mA1 += hk1.y * wA.y; mA2 += hk1.y * wA.z; mA3 += hk1.y * wA.w;
                mB0 += hk1.y * wB.x; mB1 += hk1.y * wB.y; mB2 += hk1.y * wB.z; mB3 += hk1.y * wB.w;
            }
        }
        float4* o0 = (float4*)(u.a.sh2 + g * HSTR + 8 * s);
        float4* o1 = (float4*)(u.a.sh2 + (g + 32) * HSTR + 8 * s);
        o0[rot]     = make_float4(lrelu(nA0), lrelu(nA1), lrelu(nA2), lrelu(nA3));
        o0[1 - rot] = make_float4(lrelu(nB0), lrelu(nB1), lrelu(nB2), lrelu(nB3));
        o1[rot]     = make_float4(lrelu(mA0), lrelu(mA1), lrelu(mA2), lrelu(mA3));
        o1[1 - rot] = make_float4(lrelu(mB0), lrelu(mB1), lrelu(mB2), lrelu(mB3));
    }
    __syncthreads();

    // ---- Stage C: layer 3, dims [4s,4s+4) for both nodes ----
    float f0, f1, f2, f3;       // node0 fx
    float q0, q1, q2, q3;       // node1 fx
    {
        const float4 b3v = ((const float4*)sb3)[s];
        float e0 = b3v.x, e1 = b3v.y, e2 = b3v.z, e3 = b3v.w;
        float o0 = 0.f, o1 = 0.f, o2 = 0.f, o3 = 0.f;
        float u0 = b3v.x, u1 = b3v.y, u2 = b3v.z, u3 = b3v.w;
        float v0 = 0.f, v1 = 0.f, v2 = 0.f, v3 = 0.f;
        const float* h2r0 = u.a.sh2 + g * HSTR;
        const float* h2r1 = u.a.sh2 + (g + 32) * HSTR;
#pragma unroll
        for (int j = 0; j < 64; j += 2) {
            const float2 ha = *(const float2*)(h2r0 + j);
            const float2 hb = *(const float2*)(h2r1 + j);
            const float4 w0 = ((const float4*)sW3)[j * 8 + s];
            const float4 w1 = ((const float4*)sW3)[(j + 1) * 8 + s];
            e0 += ha.x * w0.x; e1 += ha.x * w0.y; e2 += ha.x * w0.z; e3 += ha.x * w0.w;
            o0 += ha.y * w1.x; o1 += ha.y * w1.y; o2 += ha.y * w1.z; o3 += ha.y * w1.w;
            u0 += hb.x * w0.x; u1 += hb.x * w0.y; u2 += hb.x * w0.z; u3 += hb.x * w0.w;
            v0 += hb.y * w1.x; v1 += hb.y * w1.y; v2 += hb.y * w1.z; v3 += hb.y * w1.w;
        }
        f0 = e0 + o0; f1 = e1 + o1; f2 = e2 + o2; f3 = e3 + o3;
        q0 = u0 + v0; q1 = u1 + v1; q2 = u2 + v2; q3 = u3 + v3;
    }

    // ---- s_j = fx @ Wa[D:]: partials over lane's 4 dims, 8-lane all-reduce
    float sj0, sj1, sj2, sj3;   // node0
    float tj0, tj1, tj2, tj3;   // node1
    {
        const float4 w0 = ((const float4*)sWaj)[4 * s + 0];
        const float4 w1 = ((const float4*)sWaj)[4 * s + 1];
        const float4 w2 = ((const float4*)sWaj)[4 * s + 2];
        const float4 w3 = ((const float4*)sWaj)[4 * s + 3];
        sj0 = f0 * w0.x + f1 * w1.x + f2 * w2.x + f3 * w3.x;
        sj1 = f0 * w0.y + f1 * w1.y + f2 * w2.y + f3 * w3.y;
        sj2 = f0 * w0.z + f1 * w1.z + f2 * w2.z + f3 * w3.z;
        sj3 = f0 * w0.w + f1 * w1.w + f2 * w2.w + f3 * w3.w;
        tj0 = q0 * w0.x + q1 * w1.x + q2 * w2.x + q3 * w3.x;
        tj1 = q0 * w0.y + q1 * w1.y + q2 * w2.y + q3 * w3.y;
        tj2 = q0 * w0.z + q1 * w1.z + q2 * w2.z + q3 * w3.z;
        tj3 = q0 * w0.w + q1 * w1.w + q2 * w2.w + q3 * w3.w;
    }
#pragma unroll
    for (int o = 1; o < 8; o <<= 1) {
        sj0 += __shfl_xor_sync(0xffffffffu, sj0, o);
        sj1 += __shfl_xor_sync(0xffffffffu, sj1, o);
        sj2 += __shfl_xor_sync(0xffffffffu, sj2, o);
        sj3 += __shfl_xor_sync(0xffffffffu, sj3, o);
        tj0 += __shfl_xor_sync(0xffffffffu, tj0, o);
        tj1 += __shfl_xor_sync(0xffffffffu, tj1, o);
        tj2 += __shfl_xor_sync(0xffffffffu, tj2, o);
        tj3 += __shfl_xor_sync(0xffffffffu, tj3, o);
    }

    // sh1/sh2 are dead, stmp aliases them: barrier before reuse
    __syncthreads();

    // ---- Epilogue: e = exp(s); transpose e*fx into stmp (stride 65:
    // bank = (4s + i + col) % 32, conflict-free; node0 col g, node1 col g+33)
    {
        const float ea0 = __expf(sj0), ea1 = __expf(sj1);
        const float ea2 = __expf(sj2), ea3 = __expf(sj3);
        const float eb0 = __expf(tj0), eb1 = __expf(tj1);
        const float eb2 = __expf(tj2), eb3 = __expf(tj3);
        const int col = 4 * s;
        float* st = u.r.stmp;
#pragma unroll
        for (int h = 0; h < 4; h++) {
            const float eh = (h == 0) ? ea0 : (h == 1) ? ea1 : (h == 2) ? ea2 : ea3;
            st[(h * 32 + col + 0) * TSTR + g] = eh * f0;
            st[(h * 32 + col + 1) * TSTR + g] = eh * f1;
            st[(h * 32 + col + 2) * TSTR + g] = eh * f2;
            st[(h * 32 + col + 3) * TSTR + g] = eh * f3;
        }
#pragma unroll
        for (int h = 0; h < 4; h++) {
            const float eh = (h == 0) ? eb0 : (h == 1) ? eb1 : (h == 2) ? eb2 : eb3;
            st[(h * 32 + col + 0) * TSTR + g + 33] = eh * q0;
            st[(h * 32 + col + 1) * TSTR + g + 33] = eh * q1;
            st[(h * 32 + col + 2) * TSTR + g + 33] = eh * q2;
            st[(h * 32 + col + 3) * TSTR + g + 33] = eh * q3;
        }
        if (s == 0) {
            u.r.stz[0 * TSTR + g] = ea0; u.r.stz[0 * TSTR + g + 33] = eb0;
            u.r.stz[1 * TSTR + g] = ea1; u.r.stz[1 * TSTR + g + 33] = eb1;
            u.r.stz[2 * TSTR + g] = ea2; u.r.stz[2 * TSTR + g + 33] = eb2;
            u.r.stz[3 * TSTR + g] = ea3; u.r.stz[3 * TSTR + g + 33] = eb3;
        }
    }
    __syncthreads();

    // ---- block reduction over 64 nodes -> partial row [128 + 4] ----
    if (t < 128) {
        const float* col = u.r.stmp + t * TSTR;
        float a0 = 0.f, a1 = 0.f, a2 = 0.f, a3 = 0.f;
#pragma unroll
        for (int n = 0; n < 32; n += 4) {
            a0 += col[n + 0]; a1 += col[n + 1];
            a2 += col[n + 2]; a3 += col[n + 3];
        }
#pragma unroll
        for (int n = 33; n < 65; n += 4) {
            a0 += col[n + 0]; a1 += col[n + 1];
            a2 += col[n + 2]; a3 += col[n + 3];
        }
        g_part[bid * 132 + t] = (a0 + a1) + (a2 + a3);
    } else if (t < 132) {
        const float* col = u.r.stz + (t - 128) * TSTR;
        float a0 = 0.f, a1 = 0.f, a2 = 0.f, a3 = 0.f;
#pragma unroll
        for (int n = 0; n < 32; n += 4) {
            a0 += col[n + 0]; a1 += col[n + 1];
            a2 += col[n + 2]; a3 += col[n + 3];
        }
#pragma unroll
        for (int n = 33; n < 65; n += 4) {
            a0 += col[n + 0]; a1 += col[n + 1];
            a2 += col[n + 2]; a3 += col[n + 3];
        }
        g_part[bid * 132 + t] = (a0 + a1) + (a2 + a3);
    }

    // ======== software grid barrier (all 128 blocks co-resident) ========
    // release: every thread fences its g_part writes, block-sync, t0 arrives.
    // Monotonic counter: arrivals in launch L wait for the
    // ceil(my/128)*128-th arrival — replay-safe without reset.
    __threadfence();
    __syncthreads();
    if (t == 0) {
        const unsigned int my = atomicAdd(&g_bar, 1u) + 1u;
        const unsigned int tgt = ((my + 127u) >> 7) << 7;
        unsigned int cur;
        do {
            asm volatile("ld.acquire.gpu.u32 %0, [%1];" : "=r"(cur) : "l"(&g_bar));
            if (cur >= tgt) break;
            __nanosleep(128);
        } while (true);
    }
    __syncthreads();   // acquire chains block-wide; also guards union reuse

    // ======== post-barrier: combine, normalize, project, write slice ====
    // stage full Ws (4096 floats = 1024 float4) + bs into smem, coalesced
    {
        float4* wsv = (float4*)u.f.ws;
        const float4* wsg = (const float4*)Ws;
        wsv[t] = wsg[t];
        wsv[t + 256] = wsg[t + 256];
        wsv[t + 512] = wsg[t + 512];
        wsv[t + 768] = wsg[t + 768];
        if (t < 32) u.f.bsv[t] = bs[t];
    }

    const int b = bid >> 4;      // this block's batch
    if (t < 132) {
        // 16 independent L2 loads, tree sum
        const float* p = g_part + (b * 16) * 132 + t;
        const float v00 = p[0 * 132],  v01 = p[1 * 132],  v02 = p[2 * 132],  v03 = p[3 * 132];
        const float v04 = p[4 * 132],  v05 = p[5 * 132],  v06 = p[6 * 132],  v07 = p[7 * 132];
        const float v08 = p[8 * 132],  v09 = p[9 * 132],  v10 = p[10 * 132], v11 = p[11 * 132];
        const float v12 = p[12 * 132], v13 = p[13 * 132], v14 = p[14 * 132], v15 = p[15 * 132];
        const float v = (((v00 + v01) + (v02 + v03)) + ((v04 + v05) + (v06 + v07)))
                      + (((v08 + v09) + (v10 + v11)) + ((v12 + v13) + (v14 + v15)));
        if (t < 128) u.f.sm[t] = v;
        else u.f.zz[t - 128] = v;
    }
    __syncthreads();
    if (t < 128) u.f.sm[t] = u.f.sm[t] / u.f.zz[t >> 5];
    __syncthreads();

    // projection: o[d] = bs[d] + sum_k sm[k]*Ws[k][d], 4-way k split
    if (t < 128) {
        const int kg = t >> 5, dd = t & 31;
        float a = 0.f;
#pragma unroll
        for (int kk = 0; kk < 32; kk++) {
            const int k = kg * 32 + kk;
            a += u.f.sm[k] * u.f.ws[k * 32 + dd];
        }
        u.f.pr2[t] = a;
    }
    __syncthreads();
    if (t < 32)
        u.f.row[t] = u.f.bsv[t] +
            ((u.f.pr2[t] + u.f.pr2[t + 32]) + (u.f.pr2[t + 64] + u.f.pr2[t + 96]));
    __syncthreads();

    // write this block's 64 rows = 512 float4 (2 per thread), coalesced
    {
        const float4 v0 = *(const float4*)(u.f.row + ((t & 7) << 2));
        out[bid * 512 + t] = v0;
        out[bid * 512 + 256 + t] = v0;   // (256 ≡ 0 mod 8 → same d4)
    }
}

extern "C" void kernel_launch(void* const* d_in, const int* in_sizes, int n_in,
                              void* d_out, int out_size)
{
    const float* x  = (const float*)d_in[0];
    const float* W1 = (const float*)d_in[1];
    const float* b1 = (const float*)d_in[2];
    const float* W2 = (const float*)d_in[3];
    const float* b2 = (const float*)d_in[4];
    const float* W3 = (const float*)d_in[5];
    const float* b3 = (const float*)d_in[6];
    const float* Wa = (const float*)d_in[7];
    // d_in[8] = ba: cancels in the softmax
    const float* Ws = (const float*)d_in[9];
    const float* bs = (const float*)d_in[10];

    k_all<<<128, 256>>>(x, W1, b1, W2, b2, W3, b3, Wa, Ws, bs, (float4*)d_out);
}